// round 9
// baseline (speedup 1.0000x reference)
#include <cuda_runtime.h>
#include <cuda_fp16.h>
#include <math.h>

#define Nn 10000
#define Ff 256
#define Oo 128
#define Kk 5
#define Ee 160000
#define NC 1408

// ---------------- scratch ----------------
__device__ __half g_xmh[Nn * Ff];
__device__ unsigned g_mkb[Nn * 8];
__device__ __half g_Y [Nn * Ff];
__device__ __half g_M [Nn * Ff];
__device__ __half g_M2[Nn * Ff];
__device__ float g_gamma[Nn * Kk];
__device__ float g_degw[Nn];
__device__ __half g_WallT[NC * Ff];     // [out_col][feature], K-contiguous
__device__ float g_ivar[Kk * Ff];
__device__ int   g_cnt[Nn];             // zero at entry; re-zeroed by scan_kernel
__device__ int   g_fill[Nn];            // zero at entry; re-zeroed by fused epilogue
__device__ int   g_rowptr[Nn + 1];
__device__ int   g_scol[Ee];
__device__ float g_sval[Ee];
__device__ int   g_maskmode;

__device__ __forceinline__ void cp_async16(unsigned smem_addr, const void* gptr, bool pred) {
    int bytes = pred ? 16 : 0;
    asm volatile("cp.async.cg.shared.global [%0], [%1], 16, %2;\n"
                 :: "r"(smem_addr), "l"(gptr), "r"(bytes));
}
__device__ __forceinline__ void cp_async_commit() {
    asm volatile("cp.async.commit_group;\n");
}
template<int N> __device__ __forceinline__ void cp_async_wait() {
    asm volatile("cp.async.wait_group %0;\n" :: "n"(N));
}

__device__ __forceinline__ float ex_relu(float cx, float cc) {
    if (cc == 0.0f) return fmaxf(cx, 0.0f);
    float sq = sqrtf(cc);
    float w  = cx / sq;
    return sq * (0.3989422804014327f * expf(-0.5f * w * w)
                 + 0.5f * w * (1.0f + erff(w * 0.70710678118654752f)));
}

// ---------------- mask dtype detection ----------------
__global__ void detect_mask_kernel(const unsigned int* m) {
    int t = threadIdx.x;
    int i32ok = 1, f32ok = 1;
    for (int i = t; i < 1024; i += 256) {
        unsigned v = m[i];
        if (v > 1u) i32ok = 0;
        if (!(v == 0u || v == 0x3F800000u)) f32ok = 0;
    }
    int allI = __syncthreads_and(i32ok);
    int allF = __syncthreads_and(f32ok);
    if (t == 0) g_maskmode = allI ? 1 : (allF ? 2 : 0);
}

// Build g_WallT[o'][f] fp16. Block = out col o', thread = f.
__global__ void prep_weights_kernel(const float* __restrict__ W,
                                    const float* __restrict__ means,
                                    const float* __restrict__ logvars) {
    int op = blockIdx.x;          // 0..1407
    int f  = threadIdx.x;         // 0..255
    int cb = op >> 7, o = op & 127;
    float w = W[f * Oo + o];
    float val;
    if (cb == 0)       val = w;
    else if (cb < 6)   val = means[(cb - 1) * Ff + f] * w;
    else               val = expf(logvars[(cb - 6) * Ff + f]) * w * w;
    g_WallT[op * Ff + f] = __float2half_rn(val);
    if (op < Kk) g_ivar[op * Ff + f] = expf(-logvars[op * Ff + f]);
}

// 4 edges per thread
__global__ void hist_kernel(const int* __restrict__ erow) {
    int i = blockIdx.x * blockDim.x + threadIdx.x;
    if (i < Ee / 4) {
        int4 r = *(const int4*)&erow[i * 4];
        atomicAdd(&g_cnt[r.x], 1);
        atomicAdd(&g_cnt[r.y], 1);
        atomicAdd(&g_cnt[r.z], 1);
        atomicAdd(&g_cnt[r.w], 1);
    }
}

// warp-shuffle exclusive scan; zeroes g_cnt after read
__global__ void scan_kernel() {
    const int t = threadIdx.x;          // 1024
    const int lane = t & 31, wid = t >> 5;
    const int CH = 10;
    int loc[CH];
    int sum = 0;
#pragma unroll
    for (int i = 0; i < CH; i++) {
        int idx = t * CH + i;
        int c = 0;
        if (idx < Nn) { c = g_cnt[idx]; g_cnt[idx] = 0; }
        loc[i] = sum; sum += c;
    }
    int inc = sum;
#pragma unroll
    for (int off = 1; off < 32; off <<= 1) {
        int v = __shfl_up_sync(0xffffffffu, inc, off);
        if (lane >= off) inc += v;
    }
    __shared__ int wsum[32];
    if (lane == 31) wsum[wid] = inc;
    __syncthreads();
    if (wid == 0) {
        int v = wsum[lane];
        int iv = v;
#pragma unroll
        for (int off = 1; off < 32; off <<= 1) {
            int u = __shfl_up_sync(0xffffffffu, iv, off);
            if (lane >= off) iv += u;
        }
        wsum[lane] = iv - v;
    }
    __syncthreads();
    int base = wsum[wid] + inc - sum;
#pragma unroll
    for (int i = 0; i < CH; i++) {
        int idx = t * CH + i;
        if (idx < Nn) g_rowptr[idx] = base + loc[i];
    }
    if (t == 1023) g_rowptr[Nn] = wsum[31] + inc;
}

// 4 edges per thread
__global__ void scatter_kernel(const int* __restrict__ erow,
                               const int* __restrict__ ecol,
                               const float* __restrict__ eval) {
    int i = blockIdx.x * blockDim.x + threadIdx.x;
    if (i < Ee / 4) {
        int4   r = *(const int4*)&erow[i * 4];
        int4   c = *(const int4*)&ecol[i * 4];
        float4 v = *(const float4*)&eval[i * 4];
        int p;
        p = g_rowptr[r.x] + atomicAdd(&g_fill[r.x], 1); g_scol[p] = c.x; g_sval[p] = v.x;
        p = g_rowptr[r.y] + atomicAdd(&g_fill[r.y], 1); g_scol[p] = c.y; g_sval[p] = v.y;
        p = g_rowptr[r.z] + atomicAdd(&g_fill[r.z], 1); g_scol[p] = c.z; g_sval[p] = v.z;
        p = g_rowptr[r.w] + atomicAdd(&g_fill[r.w], 1); g_scol[p] = c.w; g_sval[p] = v.w;
    }
}

// Per node: xm (fp16) / mask-bits / gamma
__global__ void mask_gamma_kernel(const float* __restrict__ x,
                                  const void* __restrict__ maskp,
                                  const float* __restrict__ means,
                                  const float* __restrict__ logp) {
    int n = blockIdx.x, t = threadIdx.x;   // 256 threads
    int idx = n * Ff + t;
    float xv = x[idx];
    int mode = g_maskmode;
    int mm;
    if (mode == 0)      mm = (((const unsigned char*)maskp)[idx] != 0);
    else if (mode == 1) mm = (((const int*)maskp)[idx] != 0);
    else                mm = (((const float*)maskp)[idx] != 0.0f);

    g_xmh[idx] = __float2half_rn(mm ? 0.0f : xv);
    int w = t >> 5, l = t & 31;
    unsigned bits = __ballot_sync(0xffffffffu, mm);
    if (l == 0) g_mkb[n * 8 + w] = bits;

    float q[Kk];
#pragma unroll
    for (int k = 0; k < Kk; k++) {
        float d = xv - means[k * Ff + t];
        q[k] = mm ? 0.0f : d * d * g_ivar[k * Ff + t];
    }
#pragma unroll
    for (int off = 16; off; off >>= 1)
#pragma unroll
        for (int k = 0; k < Kk; k++)
            q[k] += __shfl_down_sync(0xffffffffu, q[k], off);

    __shared__ float sq[8][Kk];
    if (l == 0)
#pragma unroll
        for (int k = 0; k < Kk; k++) sq[w][k] = q[k];
    __syncthreads();
    if (t == 0) {
        float logit[Kk];
#pragma unroll
        for (int k = 0; k < Kk; k++) {
            float s = 0.0f;
            for (int w2 = 0; w2 < 8; w2++) s += sq[w2][k];
            logit[k] = logp[k] - 0.5f * s;
        }
        float mx = logit[0];
#pragma unroll
        for (int k = 1; k < Kk; k++) mx = fmaxf(mx, logit[k]);
        float se = 0.0f, e[Kk];
#pragma unroll
        for (int k = 0; k < Kk; k++) { e[k] = expf(logit[k] - mx); se += e[k]; }
#pragma unroll
        for (int k = 0; k < Kk; k++) g_gamma[n * Kk + k] = e[k] / se;
    }
}

// CSR SPMM, vectorized gather: 8 warps = 8 neighbor slots; each thread owns 8
// features via one uint4 (LDG.128). 8-way partials reduced through smem.
__global__ void spmm_kernel() {
    int n = blockIdx.x, t = threadIdx.x;   // 256 threads
    const int g = t >> 5, l = t & 31;      // g: neighbor slot, l: feature octet
    int s = g_rowptr[n], e = g_rowptr[n + 1];
    __shared__ int   sc[128];
    __shared__ float sv[128];
    __shared__ float red[3][8][256];
    __shared__ float sdw[8];

    float aY[8], aM[8], aM2[8];
#pragma unroll
    for (int i = 0; i < 8; i++) { aY[i] = 0.0f; aM[i] = 0.0f; aM2[i] = 0.0f; }
    float dw = 0.0f;

    for (int base = s; base < e; base += 128) {
        int cnt = min(128, e - base);
        if (t < cnt) { sc[t] = g_scol[base + t]; sv[t] = g_sval[base + t]; }
        __syncthreads();
        for (int j = g; j < cnt; j += 8) {
            int c = sc[j]; float v = sv[j];
            uint4 xw = *(const uint4*)&g_xmh[c * Ff + l * 8];
            unsigned mb = (g_mkb[c * 8 + (l >> 2)] >> ((l & 3) * 8)) & 0xFFu;
            dw += v;
            float v2 = v * v;
            float2 f0 = __half22float2(*(__half2*)&xw.x);
            float2 f1 = __half22float2(*(__half2*)&xw.y);
            float2 f2 = __half22float2(*(__half2*)&xw.z);
            float2 f3 = __half22float2(*(__half2*)&xw.w);
            float xs[8] = { f0.x, f0.y, f1.x, f1.y, f2.x, f2.y, f3.x, f3.y };
#pragma unroll
            for (int i = 0; i < 8; i++) {
                float bit = (float)((mb >> i) & 1u);
                aY [i] += v  * xs[i];
                aM [i] += v  * bit;
                aM2[i] += v2 * bit;
            }
        }
        __syncthreads();
    }

#pragma unroll
    for (int i = 0; i < 8; i++) {
        red[0][g][l * 8 + i] = aY[i];
        red[1][g][l * 8 + i] = aM[i];
        red[2][g][l * 8 + i] = aM2[i];
    }
    if (l == 0) sdw[g] = dw;
    __syncthreads();

    float rY = 0.0f, rM = 0.0f, rM2 = 0.0f;
#pragma unroll
    for (int gg = 0; gg < 8; gg++) {
        rY  += red[0][gg][t];
        rM  += red[1][gg][t];
        rM2 += red[2][gg][t];
    }
    int idx = n * Ff + t;
    g_Y [idx] = __float2half_rn(rY);
    g_M [idx] = __float2half_rn(rM);
    g_M2[idx] = __float2half_rn(rM2);
    if (t == 0) {
        float d = 0.0f;
        for (int gg = 0; gg < 8; gg++) d += sdw[gg];
        g_degw[n] = d;
    }
}

// ---------------- fused GEMM (11 panels) + ex_relu + gamma reduction ----------------
#define TSH 40
#define A_BUFH (3 * 64 * TSH)
#define B_BUFH (352 * TSH)
#define FUSED_SMEM ((2 * (A_BUFH + B_BUFH)) * 2)

__global__ __launch_bounds__(256) void fused_kernel(const float* __restrict__ bias,
                                                    float* __restrict__ out) {
    extern __shared__ __half sm[];
    __half* Bsm = sm + 2 * A_BUFH;

    const int q  = blockIdx.x;   // 0..3
    const int rb = blockIdx.y;   // 0..156
    const int tid  = threadIdx.x;
    const int lane = tid & 31, wid = tid >> 5;
    const int rw = wid & 3, cw = wid >> 2;
    const int lr = lane >> 2, lc = lane & 3;
    const int rowbase = rb * 64;

    if (q == 0 && tid < 64 && rowbase + tid < Nn) g_fill[rowbase + tid] = 0;

    unsigned as_base = (unsigned)__cvta_generic_to_shared(sm);
    unsigned bs_base = (unsigned)__cvta_generic_to_shared(Bsm);

    const __half* Amats[3] = { g_Y, g_M, g_M2 };

    float acc[11][2][4];
#pragma unroll
    for (int p = 0; p < 11; p++)
#pragma unroll
        for (int nt = 0; nt < 2; nt++)
#pragma unroll
            for (int i = 0; i < 4; i++) acc[p][nt][i] = 0.0f;

#define LOAD_TILE(KT, BUF) do {                                                        \
        _Pragma("unroll")                                                              \
        for (int i = 0; i < 3; i++) {                                                  \
            int c = tid + i * 256;                                                     \
            int mat = c >> 8, rr = (c >> 2) & 63, off = (c & 3) * 8;                   \
            int grow = rowbase + rr;                                                   \
            unsigned dst = as_base + (unsigned)((((BUF) * 3 + mat) * 64 + rr) * TSH + off) * 2u; \
            cp_async16(dst, Amats[mat] + (size_t)grow * Ff + (KT) + off, grow < Nn);   \
        }                                                                              \
        _Pragma("unroll")                                                              \
        for (int i = 0; i < 6; i++) {                                                  \
            int c = tid + i * 256;                                                     \
            if (c < 1408) {                                                            \
                int brow = c >> 2, off = (c & 3) * 8;                                  \
                int panel = brow >> 5, rip = brow & 31;                                \
                unsigned dst = bs_base + (unsigned)(((BUF) * 352 + brow) * TSH + off) * 2u; \
                cp_async16(dst, g_WallT + (size_t)(panel * 128 + q * 32 + rip) * Ff + (KT) + off, true); \
            }                                                                          \
        }                                                                              \
    } while (0)

    LOAD_TILE(0, 0);
    cp_async_commit();

    for (int kt = 0; kt < 8; kt++) {
        if (kt < 7) {
            LOAD_TILE((kt + 1) * 32, (kt + 1) & 1);
            cp_async_commit();
            cp_async_wait<1>();
        } else {
            cp_async_wait<0>();
        }
        __syncthreads();

        const __half* Ab = sm + (kt & 1) * A_BUFH;
        const __half* Bb = Bsm + (kt & 1) * B_BUFH;
#pragma unroll
        for (int ks = 0; ks < 2; ks++) {
            const int kb = ks * 16;
            unsigned af[3][4];
#pragma unroll
            for (int mat = 0; mat < 3; mat++) {
                const __half* Am = Ab + mat * 64 * TSH;
                int mr = rw * 16 + lr;
                af[mat][0] = *(const unsigned*)&Am[ mr      * TSH + kb + 2 * lc    ];
                af[mat][1] = *(const unsigned*)&Am[(mr + 8) * TSH + kb + 2 * lc    ];
                af[mat][2] = *(const unsigned*)&Am[ mr      * TSH + kb + 2 * lc + 8];
                af[mat][3] = *(const unsigned*)&Am[(mr + 8) * TSH + kb + 2 * lc + 8];
            }
#pragma unroll
            for (int p = 0; p < 11; p++) {
                const unsigned* a = af[(p == 0) ? 0 : ((p < 6) ? 1 : 2)];
#pragma unroll
                for (int nt = 0; nt < 2; nt++) {
                    int brow = p * 32 + cw * 16 + nt * 8 + lr;
                    unsigned b0 = *(const unsigned*)&Bb[brow * TSH + kb + 2 * lc    ];
                    unsigned b1 = *(const unsigned*)&Bb[brow * TSH + kb + 2 * lc + 8];
                    asm volatile(
                        "mma.sync.aligned.m16n8k16.row.col.f32.f16.f16.f32 "
                        "{%0,%1,%2,%3}, {%4,%5,%6,%7}, {%8,%9}, {%0,%1,%2,%3};"
                        : "+f"(acc[p][nt][0]), "+f"(acc[p][nt][1]),
                          "+f"(acc[p][nt][2]), "+f"(acc[p][nt][3])
                        : "r"(a[0]), "r"(a[1]), "r"(a[2]), "r"(a[3]),
                          "r"(b0), "r"(b1));
                }
            }
        }
        __syncthreads();
    }
#undef LOAD_TILE

#pragma unroll
    for (int h = 0; h < 2; h++) {
        int n = rowbase + rw * 16 + h * 8 + lr;
        if (n >= Nn) continue;
        float ga[Kk];
#pragma unroll
        for (int k = 0; k < Kk; k++) ga[k] = g_gamma[n * Kk + k];
        float dw = g_degw[n];
#pragma unroll
        for (int nt = 0; nt < 2; nt++) {
            int o = q * 32 + cw * 16 + nt * 8 + 2 * lc;
            float b0 = bias[o], b1 = bias[o + 1];
            float y0 = acc[0][nt][h * 2 + 0];
            float y1 = acc[0][nt][h * 2 + 1];
            float r0 = 0.0f, r1 = 0.0f;
#pragma unroll
            for (int k = 0; k < Kk; k++) {
                float cx0 = y0 + acc[1 + k][nt][h * 2 + 0] + dw * b0;
                float cx1 = y1 + acc[1 + k][nt][h * 2 + 1] + dw * b1;
                float cc0 = acc[6 + k][nt][h * 2 + 0];
                float cc1 = acc[6 + k][nt][h * 2 + 1];
                r0 += ga[k] * ex_relu(cx0, cc0);
                r1 += ga[k] * ex_relu(cx1, cc1);
            }
            *(float2*)&out[(size_t)n * Oo + o] = make_float2(r0, r1);
        }
    }
}

extern "C" void kernel_launch(void* const* d_in, const int* in_sizes, int n_in,
                              void* d_out, int out_size) {
    const float* x_vals  = (const float*)d_in[0];
    const void*  x_mask  = (const void*) d_in[1];
    const int*   erow    = (const int*)  d_in[2];
    const int*   ecol    = (const int*)  d_in[3];
    const float* eval    = (const float*)d_in[4];
    const float* logp    = (const float*)d_in[5];
    const float* means   = (const float*)d_in[6];
    const float* logvars = (const float*)d_in[7];
    const float* weight  = (const float*)d_in[8];
    const float* bias    = (const float*)d_in[9];
    float* out = (float*)d_out;
    (void)in_sizes; (void)n_in; (void)out_size;

    static cudaStream_t s2 = 0;
    static cudaEvent_t evFork = 0, evJoin = 0;
    if (!s2) {
        cudaFuncSetAttribute(fused_kernel, cudaFuncAttributeMaxDynamicSharedMemorySize, FUSED_SMEM);
        cudaStreamCreateWithFlags(&s2, cudaStreamNonBlocking);
        cudaEventCreateWithFlags(&evFork, cudaEventDisableTiming);
        cudaEventCreateWithFlags(&evJoin, cudaEventDisableTiming);
    }

    cudaEventRecord(evFork, 0);
    cudaStreamWaitEvent(s2, evFork, 0);

    detect_mask_kernel<<<1, 256, 0, s2>>>((const unsigned int*)x_mask);
    prep_weights_kernel<<<NC, 256, 0, s2>>>(weight, means, logvars);
    mask_gamma_kernel<<<Nn, 256, 0, s2>>>(x_vals, x_mask, means, logp);
    cudaEventRecord(evJoin, s2);

    hist_kernel<<<(Ee / 4 + 255) / 256, 256>>>(erow);
    scan_kernel<<<1, 1024>>>();
    scatter_kernel<<<(Ee / 4 + 255) / 256, 256>>>(erow, ecol, eval);

    cudaStreamWaitEvent(0, evJoin, 0);

    spmm_kernel<<<Nn, 256>>>();
    dim3 fg(4, (Nn + 63) / 64);
    fused_kernel<<<fg, 256, FUSED_SMEM>>>(bias, out);
}

// round 12
// speedup vs baseline: 1.5192x; 1.5192x over previous
#include <cuda_runtime.h>
#include <cuda_fp16.h>
#include <math.h>

#define Nn 10000
#define Ff 256
#define Oo 128
#define Kk 5
#define Ee 160000
#define NC 1408

// ---------------- scratch ----------------
__device__ __half g_xmh[Nn * Ff];
__device__ unsigned g_mkb[Nn * 8];
__device__ __half g_Y [Nn * Ff];
__device__ __half g_M [Nn * Ff];
__device__ __half g_M2[Nn * Ff];
__device__ float g_gamma[Nn * Kk];
__device__ float g_degw[Nn];
__device__ __half g_WallT[NC * Ff];     // [out_col][feature], K-contiguous
__device__ float g_ivar[Kk * Ff];
__device__ int   g_cnt[Nn];             // zero at entry; re-zeroed by scan_kernel
__device__ int   g_fill[Nn];            // zero at entry; re-zeroed by fused epilogue
__device__ int   g_rowptr[Nn + 1];
__device__ int   g_scol[Ee];
__device__ float g_sval[Ee];
__device__ int   g_maskmode;

__device__ __forceinline__ void cp_async16(unsigned smem_addr, const void* gptr, bool pred) {
    int bytes = pred ? 16 : 0;
    asm volatile("cp.async.cg.shared.global [%0], [%1], 16, %2;\n"
                 :: "r"(smem_addr), "l"(gptr), "r"(bytes));
}
__device__ __forceinline__ void cp_async_commit() {
    asm volatile("cp.async.commit_group;\n");
}
template<int N> __device__ __forceinline__ void cp_async_wait() {
    asm volatile("cp.async.wait_group %0;\n" :: "n"(N));
}

__device__ __forceinline__ __half2 u32_as_half2(unsigned u) {
    __half2 h;
    memcpy(&h, &u, sizeof(h));   // register mov — no local demotion
    return h;
}

__device__ __forceinline__ float ex_relu(float cx, float cc) {
    if (cc == 0.0f) return fmaxf(cx, 0.0f);
    float sq = sqrtf(cc);
    float w  = cx / sq;
    return sq * (0.3989422804014327f * expf(-0.5f * w * w)
                 + 0.5f * w * (1.0f + erff(w * 0.70710678118654752f)));
}

// ---------------- mask dtype detection ----------------
__global__ void detect_mask_kernel(const unsigned int* m) {
    int t = threadIdx.x;
    int i32ok = 1, f32ok = 1;
    for (int i = t; i < 1024; i += 256) {
        unsigned v = m[i];
        if (v > 1u) i32ok = 0;
        if (!(v == 0u || v == 0x3F800000u)) f32ok = 0;
    }
    int allI = __syncthreads_and(i32ok);
    int allF = __syncthreads_and(f32ok);
    if (t == 0) g_maskmode = allI ? 1 : (allF ? 2 : 0);
}

// Build g_WallT[o'][f] fp16. Block = out col o', thread = f.
__global__ void prep_weights_kernel(const float* __restrict__ W,
                                    const float* __restrict__ means,
                                    const float* __restrict__ logvars) {
    int op = blockIdx.x;          // 0..1407
    int f  = threadIdx.x;         // 0..255
    int cb = op >> 7, o = op & 127;
    float w = W[f * Oo + o];
    float val;
    if (cb == 0)       val = w;
    else if (cb < 6)   val = means[(cb - 1) * Ff + f] * w;
    else               val = expf(logvars[(cb - 6) * Ff + f]) * w * w;
    g_WallT[op * Ff + f] = __float2half_rn(val);
    if (op < Kk) g_ivar[op * Ff + f] = expf(-logvars[op * Ff + f]);
}

__global__ void hist_kernel(const int* __restrict__ erow) {
    int e = blockIdx.x * blockDim.x + threadIdx.x;
    if (e < Ee) atomicAdd(&g_cnt[erow[e]], 1);
}

// warp-shuffle exclusive scan; zeroes g_cnt after read
__global__ void scan_kernel() {
    const int t = threadIdx.x;          // 1024
    const int lane = t & 31, wid = t >> 5;
    const int CH = 10;
    int loc[CH];
    int sum = 0;
#pragma unroll
    for (int i = 0; i < CH; i++) {
        int idx = t * CH + i;
        int c = 0;
        if (idx < Nn) { c = g_cnt[idx]; g_cnt[idx] = 0; }
        loc[i] = sum; sum += c;
    }
    int inc = sum;
#pragma unroll
    for (int off = 1; off < 32; off <<= 1) {
        int v = __shfl_up_sync(0xffffffffu, inc, off);
        if (lane >= off) inc += v;
    }
    __shared__ int wsum[32];
    if (lane == 31) wsum[wid] = inc;
    __syncthreads();
    if (wid == 0) {
        int v = wsum[lane];
        int iv = v;
#pragma unroll
        for (int off = 1; off < 32; off <<= 1) {
            int u = __shfl_up_sync(0xffffffffu, iv, off);
            if (lane >= off) iv += u;
        }
        wsum[lane] = iv - v;
    }
    __syncthreads();
    int base = wsum[wid] + inc - sum;
#pragma unroll
    for (int i = 0; i < CH; i++) {
        int idx = t * CH + i;
        if (idx < Nn) g_rowptr[idx] = base + loc[i];
    }
    if (t == 1023) g_rowptr[Nn] = wsum[31] + inc;
}

__global__ void scatter_kernel(const int* __restrict__ erow,
                               const int* __restrict__ ecol,
                               const float* __restrict__ eval) {
    int e = blockIdx.x * blockDim.x + threadIdx.x;
    if (e < Ee) {
        int r = erow[e];
        int pos = g_rowptr[r] + atomicAdd(&g_fill[r], 1);
        g_scol[pos] = ecol[e];
        g_sval[pos] = eval[e];
    }
}

// Per node: xm (fp16) / mask-bits / gamma
__global__ void mask_gamma_kernel(const float* __restrict__ x,
                                  const void* __restrict__ maskp,
                                  const float* __restrict__ means,
                                  const float* __restrict__ logp) {
    int n = blockIdx.x, t = threadIdx.x;   // 256 threads
    int idx = n * Ff + t;
    float xv = x[idx];
    int mode = g_maskmode;
    int mm;
    if (mode == 0)      mm = (((const unsigned char*)maskp)[idx] != 0);
    else if (mode == 1) mm = (((const int*)maskp)[idx] != 0);
    else                mm = (((const float*)maskp)[idx] != 0.0f);

    g_xmh[idx] = __float2half_rn(mm ? 0.0f : xv);
    int w = t >> 5, l = t & 31;
    unsigned bits = __ballot_sync(0xffffffffu, mm);
    if (l == 0) g_mkb[n * 8 + w] = bits;

    float q[Kk];
#pragma unroll
    for (int k = 0; k < Kk; k++) {
        float d = xv - means[k * Ff + t];
        q[k] = mm ? 0.0f : d * d * g_ivar[k * Ff + t];
    }
#pragma unroll
    for (int off = 16; off; off >>= 1)
#pragma unroll
        for (int k = 0; k < Kk; k++)
            q[k] += __shfl_down_sync(0xffffffffu, q[k], off);

    __shared__ float sq[8][Kk];
    if (l == 0)
#pragma unroll
        for (int k = 0; k < Kk; k++) sq[w][k] = q[k];
    __syncthreads();
    if (t == 0) {
        float logit[Kk];
#pragma unroll
        for (int k = 0; k < Kk; k++) {
            float s = 0.0f;
            for (int w2 = 0; w2 < 8; w2++) s += sq[w2][k];
            logit[k] = logp[k] - 0.5f * s;
        }
        float mx = logit[0];
#pragma unroll
        for (int k = 1; k < Kk; k++) mx = fmaxf(mx, logit[k]);
        float se = 0.0f, e[Kk];
#pragma unroll
        for (int k = 0; k < Kk; k++) { e[k] = expf(logit[k] - mx); se += e[k]; }
#pragma unroll
        for (int k = 0; k < Kk; k++) g_gamma[n * Kk + k] = e[k] / se;
    }
}

// CSR SPMM: 4 groups x 64 threads; each thread owns a feature quad (uint2 = LDG.64).
// Groups process interleaved neighbors; 4-way partials reduced through 12KB smem.
__global__ void spmm_kernel() {
    int n = blockIdx.x, t = threadIdx.x;   // 256 threads
    const int grp = t >> 6;                // 0..3 neighbor slot
    const int ft  = t & 63;                // feature quad: features 4ft..4ft+3
    int s = g_rowptr[n], e = g_rowptr[n + 1];
    __shared__ int   sc[128];
    __shared__ float sv[128];
    __shared__ float red[3][4][256];
    __shared__ float sdw[4];

    float aY0 = 0.f, aY1 = 0.f, aY2 = 0.f, aY3 = 0.f;
    float aM0 = 0.f, aM1 = 0.f, aM2_ = 0.f, aM3 = 0.f;
    float b0 = 0.f, b1 = 0.f, b2 = 0.f, b3 = 0.f;
    float dw = 0.0f;

    for (int base = s; base < e; base += 128) {
        int cnt = min(128, e - base);
        if (t < cnt) { sc[t] = g_scol[base + t]; sv[t] = g_sval[base + t]; }
        __syncthreads();
        for (int j = grp; j < cnt; j += 4) {
            int c = sc[j]; float v = sv[j];
            float v2 = v * v;
            uint2 xw = *(const uint2*)&g_xmh[c * Ff + ft * 4];
            unsigned mw = g_mkb[c * 8 + (ft >> 3)];
            unsigned mb = (mw >> ((ft & 7) * 4)) & 0xFu;
            float2 f0 = __half22float2(u32_as_half2(xw.x));
            float2 f1 = __half22float2(u32_as_half2(xw.y));
            float m0 = (float)(mb & 1u),        m1 = (float)((mb >> 1) & 1u);
            float m2 = (float)((mb >> 2) & 1u), m3 = (float)((mb >> 3) & 1u);
            dw += v;
            aY0 += v * f0.x;  aY1 += v * f0.y;  aY2 += v * f1.x;  aY3 += v * f1.y;
            aM0 += v * m0;    aM1 += v * m1;    aM2_ += v * m2;   aM3 += v * m3;
            b0  += v2 * m0;   b1  += v2 * m1;   b2  += v2 * m2;   b3  += v2 * m3;
        }
        __syncthreads();
    }

    red[0][grp][ft * 4 + 0] = aY0; red[0][grp][ft * 4 + 1] = aY1;
    red[0][grp][ft * 4 + 2] = aY2; red[0][grp][ft * 4 + 3] = aY3;
    red[1][grp][ft * 4 + 0] = aM0; red[1][grp][ft * 4 + 1] = aM1;
    red[1][grp][ft * 4 + 2] = aM2_; red[1][grp][ft * 4 + 3] = aM3;
    red[2][grp][ft * 4 + 0] = b0;  red[2][grp][ft * 4 + 1] = b1;
    red[2][grp][ft * 4 + 2] = b2;  red[2][grp][ft * 4 + 3] = b3;
    if (ft == 0) sdw[grp] = dw;
    __syncthreads();

    float rY = 0.f, rM = 0.f, rM2 = 0.f;
#pragma unroll
    for (int g = 0; g < 4; g++) {
        rY  += red[0][g][t];
        rM  += red[1][g][t];
        rM2 += red[2][g][t];
    }
    int idx = n * Ff + t;
    g_Y [idx] = __float2half_rn(rY);
    g_M [idx] = __float2half_rn(rM);
    g_M2[idx] = __float2half_rn(rM2);
    if (t == 0) g_degw[n] = sdw[0] + sdw[1] + sdw[2] + sdw[3];
}

// ---------------- fused GEMM (11 panels) + ex_relu + gamma reduction ----------------
#define TSH 40
#define A_BUFH (3 * 64 * TSH)
#define B_BUFH (352 * TSH)
#define FUSED_SMEM ((2 * (A_BUFH + B_BUFH)) * 2)

__global__ __launch_bounds__(256) void fused_kernel(const float* __restrict__ bias,
                                                    float* __restrict__ out) {
    extern __shared__ __half sm[];
    __half* Bsm = sm + 2 * A_BUFH;

    const int q  = blockIdx.x;   // 0..3
    const int rb = blockIdx.y;   // 0..156
    const int tid  = threadIdx.x;
    const int lane = tid & 31, wid = tid >> 5;
    const int rw = wid & 3, cw = wid >> 2;
    const int lr = lane >> 2, lc = lane & 3;
    const int rowbase = rb * 64;

    if (q == 0 && tid < 64 && rowbase + tid < Nn) g_fill[rowbase + tid] = 0;

    unsigned as_base = (unsigned)__cvta_generic_to_shared(sm);
    unsigned bs_base = (unsigned)__cvta_generic_to_shared(Bsm);

    const __half* Amats[3] = { g_Y, g_M, g_M2 };

    float acc[11][2][4];
#pragma unroll
    for (int p = 0; p < 11; p++)
#pragma unroll
        for (int nt = 0; nt < 2; nt++)
#pragma unroll
            for (int i = 0; i < 4; i++) acc[p][nt][i] = 0.0f;

#define LOAD_TILE(KT, BUF) do {                                                        \
        _Pragma("unroll")                                                              \
        for (int i = 0; i < 3; i++) {                                                  \
            int c = tid + i * 256;                                                     \
            int mat = c >> 8, rr = (c >> 2) & 63, off = (c & 3) * 8;                   \
            int grow = rowbase + rr;                                                   \
            unsigned dst = as_base + (unsigned)((((BUF) * 3 + mat) * 64 + rr) * TSH + off) * 2u; \
            cp_async16(dst, Amats[mat] + (size_t)grow * Ff + (KT) + off, grow < Nn);   \
        }                                                                              \
        _Pragma("unroll")                                                              \
        for (int i = 0; i < 6; i++) {                                                  \
            int c = tid + i * 256;                                                     \
            if (c < 1408) {                                                            \
                int brow = c >> 2, off = (c & 3) * 8;                                  \
                int panel = brow >> 5, rip = brow & 31;                                \
                unsigned dst = bs_base + (unsigned)(((BUF) * 352 + brow) * TSH + off) * 2u; \
                cp_async16(dst, g_WallT + (size_t)(panel * 128 + q * 32 + rip) * Ff + (KT) + off, true); \
            }                                                                          \
        }                                                                              \
    } while (0)

    LOAD_TILE(0, 0);
    cp_async_commit();

    for (int kt = 0; kt < 8; kt++) {
        if (kt < 7) {
            LOAD_TILE((kt + 1) * 32, (kt + 1) & 1);
            cp_async_commit();
            cp_async_wait<1>();
        } else {
            cp_async_wait<0>();
        }
        __syncthreads();

        const __half* Ab = sm + (kt & 1) * A_BUFH;
        const __half* Bb = Bsm + (kt & 1) * B_BUFH;
#pragma unroll
        for (int ks = 0; ks < 2; ks++) {
            const int kb = ks * 16;
            unsigned af[3][4];
#pragma unroll
            for (int mat = 0; mat < 3; mat++) {
                const __half* Am = Ab + mat * 64 * TSH;
                int mr = rw * 16 + lr;
                af[mat][0] = *(const unsigned*)&Am[ mr      * TSH + kb + 2 * lc    ];
                af[mat][1] = *(const unsigned*)&Am[(mr + 8) * TSH + kb + 2 * lc    ];
                af[mat][2] = *(const unsigned*)&Am[ mr      * TSH + kb + 2 * lc + 8];
                af[mat][3] = *(const unsigned*)&Am[(mr + 8) * TSH + kb + 2 * lc + 8];
            }
#pragma unroll
            for (int p = 0; p < 11; p++) {
                const unsigned* a = af[(p == 0) ? 0 : ((p < 6) ? 1 : 2)];
#pragma unroll
                for (int nt = 0; nt < 2; nt++) {
                    int brow = p * 32 + cw * 16 + nt * 8 + lr;
                    unsigned bb0 = *(const unsigned*)&Bb[brow * TSH + kb + 2 * lc    ];
                    unsigned bb1 = *(const unsigned*)&Bb[brow * TSH + kb + 2 * lc + 8];
                    asm volatile(
                        "mma.sync.aligned.m16n8k16.row.col.f32.f16.f16.f32 "
                        "{%0,%1,%2,%3}, {%4,%5,%6,%7}, {%8,%9}, {%0,%1,%2,%3};"
                        : "+f"(acc[p][nt][0]), "+f"(acc[p][nt][1]),
                          "+f"(acc[p][nt][2]), "+f"(acc[p][nt][3])
                        : "r"(a[0]), "r"(a[1]), "r"(a[2]), "r"(a[3]),
                          "r"(bb0), "r"(bb1));
                }
            }
        }
        __syncthreads();
    }
#undef LOAD_TILE

#pragma unroll
    for (int h = 0; h < 2; h++) {
        int n = rowbase + rw * 16 + h * 8 + lr;
        if (n >= Nn) continue;
        float ga[Kk];
#pragma unroll
        for (int k = 0; k < Kk; k++) ga[k] = g_gamma[n * Kk + k];
        float dw = g_degw[n];
#pragma unroll
        for (int nt = 0; nt < 2; nt++) {
            int o = q * 32 + cw * 16 + nt * 8 + 2 * lc;
            float bb0 = bias[o], bb1 = bias[o + 1];
            float y0 = acc[0][nt][h * 2 + 0];
            float y1 = acc[0][nt][h * 2 + 1];
            float r0 = 0.0f, r1 = 0.0f;
#pragma unroll
            for (int k = 0; k < Kk; k++) {
                float cx0 = y0 + acc[1 + k][nt][h * 2 + 0] + dw * bb0;
                float cx1 = y1 + acc[1 + k][nt][h * 2 + 1] + dw * bb1;
                float cc0 = acc[6 + k][nt][h * 2 + 0];
                float cc1 = acc[6 + k][nt][h * 2 + 1];
                r0 += ga[k] * ex_relu(cx0, cc0);
                r1 += ga[k] * ex_relu(cx1, cc1);
            }
            *(float2*)&out[(size_t)n * Oo + o] = make_float2(r0, r1);
        }
    }
}

extern "C" void kernel_launch(void* const* d_in, const int* in_sizes, int n_in,
                              void* d_out, int out_size) {
    const float* x_vals  = (const float*)d_in[0];
    const void*  x_mask  = (const void*) d_in[1];
    const int*   erow    = (const int*)  d_in[2];
    const int*   ecol    = (const int*)  d_in[3];
    const float* eval    = (const float*)d_in[4];
    const float* logp    = (const float*)d_in[5];
    const float* means   = (const float*)d_in[6];
    const float* logvars = (const float*)d_in[7];
    const float* weight  = (const float*)d_in[8];
    const float* bias    = (const float*)d_in[9];
    float* out = (float*)d_out;
    (void)in_sizes; (void)n_in; (void)out_size;

    static cudaStream_t s2 = 0;
    static cudaEvent_t evFork = 0, evJoin = 0;
    if (!s2) {
        cudaFuncSetAttribute(fused_kernel, cudaFuncAttributeMaxDynamicSharedMemorySize, FUSED_SMEM);
        cudaStreamCreateWithFlags(&s2, cudaStreamNonBlocking);
        cudaEventCreateWithFlags(&evFork, cudaEventDisableTiming);
        cudaEventCreateWithFlags(&evJoin, cudaEventDisableTiming);
    }

    cudaEventRecord(evFork, 0);
    cudaStreamWaitEvent(s2, evFork, 0);

    detect_mask_kernel<<<1, 256, 0, s2>>>((const unsigned int*)x_mask);
    prep_weights_kernel<<<NC, 256, 0, s2>>>(weight, means, logvars);
    mask_gamma_kernel<<<Nn, 256, 0, s2>>>(x_vals, x_mask, means, logp);
    cudaEventRecord(evJoin, s2);

    hist_kernel<<<(Ee + 255) / 256, 256>>>(erow);
    scan_kernel<<<1, 1024>>>();
    scatter_kernel<<<(Ee + 255) / 256, 256>>>(erow, ecol, eval);

    cudaStreamWaitEvent(0, evJoin, 0);

    spmm_kernel<<<Nn, 256>>>();
    dim3 fg(4, (Nn + 63) / 64);
    fused_kernel<<<fg, 256, FUSED_SMEM>>>(bias, out);
}